// round 4
// baseline (speedup 1.0000x reference)
#include <cuda_runtime.h>
#include <cstddef>

// Two-layer LSTM recurrence, persistent kernel, j-paired f32x2 GEMV.
// Accumulators per (gate,batch) hold (even-j, odd-j) partial sums; both W and
// h are stored pre-paired over j, so the inner loop has NO packing movs and
// NO duplicated shared-memory bytes (minimal crossbar traffic).
//
// 128 blocks x 448 threads:
//   tid <  400 : layer-1. unit u = tid>>2, batch group t4 = tid&3, BT=8.
//   416<=tid<448: layer-2 (one warp; lane = batch elem), pipelined 1 step
//                 behind layer-1 during the observed phase.

#define CELL     100
#define NJ2      50       // CELL/2 j-pairs
#define NB       32       // batch per block
#define BT       8        // batch per layer-1 thread
#define THREADS  448
#define L2BASE   416
#define WSTRIDE  404      // floats per unit row of Wint (conflict-free banks)

#define FMA2(acc, a, b) asm("fma.rn.f32x2 %0,%1,%2,%0;" : "+l"(acc) : "l"(a), "l"(b))
#define UNPK2(lo, hi, s) asm("mov.b64 {%0,%1},%2;" : "=f"(lo), "=f"(hi) : "l"(s))

__device__ __forceinline__ float sigm(float x) {
    return 1.0f / (1.0f + __expf(-x));
}
__device__ __forceinline__ float tanh_f(float x) {
    float e = __expf(2.0f * x);
    return 1.0f - 2.0f / (e + 1.0f);
}

__global__ void __launch_bounds__(THREADS, 1)
tsrnn_kernel(const float* __restrict__ input,
             const float* __restrict__ W_ih1, const float* __restrict__ W_hh1,
             const float* __restrict__ b_ih1, const float* __restrict__ b_hh1,
             const float* __restrict__ W_ih2, const float* __restrict__ W_hh2,
             const float* __restrict__ b_ih2, const float* __restrict__ b_hh2,
             float* __restrict__ out, int T, int FUT, int Btot)
{
    extern __shared__ float sm[];
    float* Wint  = sm;                      // [100][WSTRIDE]: u*404 + j2*8 + k*2 + p
    float* hpair = Wint  + CELL * WSTRIDE;  // [50][64]: (h_{2j2}[b], h_{2j2+1}[b])
    float* c1sh  = hpair + NJ2 * 64;        // [100][32]
    float* w2i   = c1sh  + CELL * NB;       // [100][4] gate-interleaved W_ih2
    float* c2sh  = w2i   + CELL * 4;        // [32]

    const int tid    = threadIdx.x;
    const int bglob0 = blockIdx.x * NB;

    const bool l1 = (tid < 400);
    const bool l2 = (tid >= L2BASE);
    const int  u  = tid >> 2;               // layer-1 unit (0..99)
    const int  t4 = tid & 3;                // batch subgroup
    const int  b0 = t4 * BT;                // first batch elem

    // ---- stage W_hh1: j-paired, gate-major within pair ----
    for (int idx = tid; idx < 4 * CELL * CELL; idx += THREADS) {
        int uu = idx / 400, rem = idx - uu * 400;
        int j2 = rem >> 3, k = (rem >> 1) & 3, p = rem & 1;
        int j  = 2 * j2 + p;
        Wint[uu * WSTRIDE + j2 * 8 + k * 2 + p] = W_hh1[(k * CELL + uu) * CELL + j];
    }
    for (int idx = tid; idx < 4 * CELL; idx += THREADS) {
        int uu = idx >> 2, k = idx & 3;
        w2i[uu * 4 + k] = W_ih2[k * CELL + uu];
    }
    for (int idx = tid; idx < NJ2 * 64; idx += THREADS) hpair[idx] = 0.0f;
    for (int idx = tid; idx < CELL * NB; idx += THREADS) c1sh[idx] = 0.0f;
    if (tid < NB) c2sh[tid] = 0.0f;

    // layer-1 per-thread constants
    float wih[4], bsum[4];
    if (l1) {
        #pragma unroll
        for (int k = 0; k < 4; k++) {
            int g = k * CELL + u;
            wih[k]  = W_ih1[g];
            bsum[k] = b_ih1[g] + b_hh1[g];
        }
    }
    // layer-2 per-lane constants + state
    const int bl2 = tid - L2BASE;           // lane = batch elem (0..31)
    float whh2[4], b2c[4];
    float h2 = 0.0f, c2 = 0.0f;
    if (l2) {
        #pragma unroll
        for (int k = 0; k < 4; k++) {
            whh2[k] = W_hh2[k];
            b2c[k]  = b_ih2[k] + b_hh2[k];
        }
    }

    float c1r[BT];
    #pragma unroll
    for (int bb = 0; bb < BT; bb++) c1r[bb] = 0.0f;

    const float* wp = Wint  + u * WSTRIDE;
    const float* hp = hpair + b0 * 2;       // pairs for b0..b0+7

    // ================= layer-1 step =================
    auto layer1_step = [&](const float* __restrict__ xv, float* __restrict__ hn) {
        unsigned long long Ai[BT], Af[BT], Ag[BT], Ao[BT];
        #pragma unroll
        for (int bb = 0; bb < BT; bb++) { Ai[bb] = 0ull; Af[bb] = 0ull; Ag[bb] = 0ull; Ao[bb] = 0ull; }

        #pragma unroll 2
        for (int j2 = 0; j2 < NJ2; j2++) {
            ulonglong2 wIF = *(const ulonglong2*)(wp + j2 * 8);      // (wi),(wf) pairs
            ulonglong2 wGO = *(const ulonglong2*)(wp + j2 * 8 + 4);  // (wg),(wo) pairs
            ulonglong2 hA = *(const ulonglong2*)(hp + j2 * 64);      // b0,b0+1
            ulonglong2 hB = *(const ulonglong2*)(hp + j2 * 64 + 4);  // b0+2,b0+3
            ulonglong2 hC = *(const ulonglong2*)(hp + j2 * 64 + 8);  // b0+4,b0+5
            ulonglong2 hD = *(const ulonglong2*)(hp + j2 * 64 + 12); // b0+6,b0+7
            FMA2(Ai[0], wIF.x, hA.x); FMA2(Af[0], wIF.y, hA.x);
            FMA2(Ag[0], wGO.x, hA.x); FMA2(Ao[0], wGO.y, hA.x);
            FMA2(Ai[1], wIF.x, hA.y); FMA2(Af[1], wIF.y, hA.y);
            FMA2(Ag[1], wGO.x, hA.y); FMA2(Ao[1], wGO.y, hA.y);
            FMA2(Ai[2], wIF.x, hB.x); FMA2(Af[2], wIF.y, hB.x);
            FMA2(Ag[2], wGO.x, hB.x); FMA2(Ao[2], wGO.y, hB.x);
            FMA2(Ai[3], wIF.x, hB.y); FMA2(Af[3], wIF.y, hB.y);
            FMA2(Ag[3], wGO.x, hB.y); FMA2(Ao[3], wGO.y, hB.y);
            FMA2(Ai[4], wIF.x, hC.x); FMA2(Af[4], wIF.y, hC.x);
            FMA2(Ag[4], wGO.x, hC.x); FMA2(Ao[4], wGO.y, hC.x);
            FMA2(Ai[5], wIF.x, hC.y); FMA2(Af[5], wIF.y, hC.y);
            FMA2(Ag[5], wGO.x, hC.y); FMA2(Ao[5], wGO.y, hC.y);
            FMA2(Ai[6], wIF.x, hD.x); FMA2(Af[6], wIF.y, hD.x);
            FMA2(Ag[6], wGO.x, hD.x); FMA2(Ao[6], wGO.y, hD.x);
            FMA2(Ai[7], wIF.x, hD.y); FMA2(Af[7], wIF.y, hD.y);
            FMA2(Ag[7], wGO.x, hD.y); FMA2(Ao[7], wGO.y, hD.y);
        }

        #pragma unroll
        for (int bb = 0; bb < BT; bb++) {
            float e, o;
            UNPK2(e, o, Ai[bb]); float gi = e + o;
            UNPK2(e, o, Af[bb]); float gf = e + o;
            UNPK2(e, o, Ag[bb]); float gg = e + o;
            UNPK2(e, o, Ao[bb]); float go = e + o;
            float pi = fmaf(xv[bb], wih[0], gi + bsum[0]);
            float pf = fmaf(xv[bb], wih[1], gf + bsum[1]);
            float pg = fmaf(xv[bb], wih[2], gg + bsum[2]);
            float po = fmaf(xv[bb], wih[3], go + bsum[3]);
            float c  = sigm(pf) * c1r[bb] + sigm(pi) * tanh_f(pg);
            c1r[bb] = c;
            hn[bb]  = sigm(po) * tanh_f(c);
        }
    };

    auto l1_write = [&](const float* __restrict__ hn) {
        // h goes into the j-paired layout: unit u -> row u>>1, slot u&1
        float* hw = hpair + (u >> 1) * 64 + b0 * 2 + (u & 1);
        #pragma unroll
        for (int i = 0; i < BT; i++) hw[2 * i] = hn[i];
        *(float4*)(c1sh + u * NB + b0)     = make_float4(c1r[0], c1r[1], c1r[2], c1r[3]);
        *(float4*)(c1sh + u * NB + b0 + 4) = make_float4(c1r[4], c1r[5], c1r[6], c1r[7]);
    };

    // ================= layer-2 step (one warp, lane = batch) =============
    auto layer2_step = [&](int tt, bool wr_out) {
        const float* cp = c1sh + bl2;
        float di = 0.f, df = 0.f, dg = 0.f, dz = 0.f;
        #pragma unroll 4
        for (int uu = 0; uu < CELL; uu++) {
            float cv  = cp[uu * NB];
            float4 w4 = *(const float4*)(w2i + uu * 4);
            di = fmaf(cv, w4.x, di);
            df = fmaf(cv, w4.y, df);
            dg = fmaf(cv, w4.z, dg);
            dz = fmaf(cv, w4.w, dz);
        }
        float pi = fmaf(h2, whh2[0], di + b2c[0]);
        float pf = fmaf(h2, whh2[1], df + b2c[1]);
        float pg = fmaf(h2, whh2[2], dg + b2c[2]);
        float po = fmaf(h2, whh2[3], dz + b2c[3]);
        float c  = sigm(pf) * c2 + sigm(pi) * tanh_f(pg);
        c2 = c;
        h2 = sigm(po) * tanh_f(c);
        c2sh[bl2] = c;
        if (wr_out) out[(size_t)(bglob0 + bl2) * FUT + (tt - T)] = c;
    };

    __syncthreads();

    // ===== observed phase: l2 pipelined one step behind, 2 syncs/step =====
    for (int t = 0; t < T; ++t) {
        float xv[BT], hn[BT];
        if (l1) {
            float4 x0 = *(const float4*)(input + (size_t)t * Btot + bglob0 + b0);
            float4 x1 = *(const float4*)(input + (size_t)t * Btot + bglob0 + b0 + 4);
            xv[0] = x0.x; xv[1] = x0.y; xv[2] = x0.z; xv[3] = x0.w;
            xv[4] = x1.x; xv[5] = x1.y; xv[6] = x1.z; xv[7] = x1.w;
            layer1_step(xv, hn);           // reads hpair (step t-1)
        } else if (l2 && t > 0) {
            layer2_step(t - 1, false);     // reads c1sh (step t-1)
        }
        __syncthreads();                   // all reads of hpair/c1sh done
        if (l1) l1_write(hn);
        __syncthreads();                   // new h/c1 visible
    }
    // drain layer-2 for step T-1
    if (l2) layer2_step(T - 1, false);
    __syncthreads();

    // ===== future phase: strictly serial, 3 syncs/step =====
    const int TOT = T + FUT;
    for (int t = T; t < TOT; ++t) {
        float xv[BT], hn[BT];
        if (l1) {
            float4 x0 = *(const float4*)(c2sh + b0);
            float4 x1 = *(const float4*)(c2sh + b0 + 4);
            xv[0] = x0.x; xv[1] = x0.y; xv[2] = x0.z; xv[3] = x0.w;
            xv[4] = x1.x; xv[5] = x1.y; xv[6] = x1.z; xv[7] = x1.w;
            layer1_step(xv, hn);
        }
        __syncthreads();
        if (l1) l1_write(hn);
        __syncthreads();
        if (l2) layer2_step(t, true);
        __syncthreads();
    }
}

extern "C" void kernel_launch(void* const* d_in, const int* in_sizes, int n_in,
                              void* d_out, int out_size)
{
    const float* input = (const float*)d_in[0];
    const float* W_ih1 = (const float*)d_in[1];
    const float* W_hh1 = (const float*)d_in[2];
    const float* b_ih1 = (const float*)d_in[3];
    const float* b_hh1 = (const float*)d_in[4];
    const float* W_ih2 = (const float*)d_in[5];
    const float* W_hh2 = (const float*)d_in[6];
    const float* b_ih2 = (const float*)d_in[7];
    const float* b_hh2 = (const float*)d_in[8];
    float* out = (float*)d_out;

    const int Btot = 4096;
    const int T    = in_sizes[0] / Btot;   // 512
    const int FUT  = out_size   / Btot;    // 64

    const int smem = (CELL * WSTRIDE     // Wint      40400
                      + NJ2 * 64         // hpair      3200
                      + CELL * NB        // c1sh       3200
                      + 4 * CELL         // w2i         400
                      + NB)              // c2sh         32
                     * (int)sizeof(float);  // = 188,928 B

    cudaFuncSetAttribute(tsrnn_kernel,
                         cudaFuncAttributeMaxDynamicSharedMemorySize, smem);

    tsrnn_kernel<<<Btot / NB, THREADS, smem>>>(
        input, W_ih1, W_hh1, b_ih1, b_hh1,
        W_ih2, W_hh2, b_ih2, b_hh2,
        out, T, FUT, Btot);
}

// round 5
// speedup vs baseline: 1.2068x; 1.2068x over previous
#include <cuda_runtime.h>
#include <cstddef>

// Two-layer LSTM recurrence, persistent kernel, j-paired f32x2 GEMV.
// R5: j-pairing (zero packs, zero duplicated bytes) at BT=4 / 800 l1 threads
// (latency hiding), with the h buffer split into two 32-word-row half
// regions so every LDS.128 is bank-conflict-free.
//
// 128 blocks x 832 threads:
//   tid <  800 : layer-1. unit u = tid>>3, batch group t8 = tid&7, BT=4.
//   tid >= 800 : layer-2 (one warp; lane = batch elem), pipelined 1 step
//                behind layer-1 during the observed phase.

#define CELL     100
#define NJ2      50       // CELL/2 j-pairs
#define NB       32       // batch per block
#define BT       4        // batch per layer-1 thread
#define THREADS  832
#define L2BASE   800
#define WSTRIDE  404      // 404 mod 32 = 20 -> 4 consecutive u hit distinct quads

#define FMA2(acc, a, b) asm("fma.rn.f32x2 %0,%1,%2,%0;" : "+l"(acc) : "l"(a), "l"(b))
#define UNPK2(lo, hi, s) asm("mov.b64 {%0,%1},%2;" : "=f"(lo), "=f"(hi) : "l"(s))

__device__ __forceinline__ float sigm(float x) {
    return 1.0f / (1.0f + __expf(-x));
}
__device__ __forceinline__ float tanh_f(float x) {
    float e = __expf(2.0f * x);
    return 1.0f - 2.0f / (e + 1.0f);
}

__global__ void __launch_bounds__(THREADS, 1)
tsrnn_kernel(const float* __restrict__ input,
             const float* __restrict__ W_ih1, const float* __restrict__ W_hh1,
             const float* __restrict__ b_ih1, const float* __restrict__ b_hh1,
             const float* __restrict__ W_ih2, const float* __restrict__ W_hh2,
             const float* __restrict__ b_ih2, const float* __restrict__ b_hh2,
             float* __restrict__ out, int T, int FUT, int Btot)
{
    extern __shared__ float sm[];
    float* Wint = sm;                     // [100][WSTRIDE]: u*404 + j2*8 + k*2 + p
    float* hA   = Wint + CELL * WSTRIDE;  // [50][32]: pairs (h_e,h_o) for b%4<2
    float* hB   = hA   + NJ2 * 32;        // [50][32]: pairs for b%4>=2
    float* c1sh = hB   + NJ2 * 32;        // [100][32]
    float* w2i  = c1sh + CELL * NB;       // [100][4] gate-interleaved W_ih2
    float* c2sh = w2i  + CELL * 4;        // [32]

    const int tid    = threadIdx.x;
    const int bglob0 = blockIdx.x * NB;

    const bool l1 = (tid < L2BASE);
    const bool l2 = (tid >= L2BASE);
    const int  u  = tid >> 3;             // layer-1 unit (0..99)
    const int  t8 = tid & 7;              // batch subgroup
    const int  b0 = t8 * BT;              // first batch elem

    // ---- stage W_hh1: j-paired, gate-major within pair ----
    for (int idx = tid; idx < 4 * CELL * CELL; idx += THREADS) {
        int uu = idx / 400, rem = idx - uu * 400;
        int j2 = rem >> 3, k = (rem >> 1) & 3, p = rem & 1;
        int j  = 2 * j2 + p;
        Wint[uu * WSTRIDE + j2 * 8 + k * 2 + p] = W_hh1[(k * CELL + uu) * CELL + j];
    }
    for (int idx = tid; idx < 4 * CELL; idx += THREADS) {
        int uu = idx >> 2, k = idx & 3;
        w2i[uu * 4 + k] = W_ih2[k * CELL + uu];
    }
    for (int idx = tid; idx < 2 * NJ2 * 32; idx += THREADS) hA[idx] = 0.0f;
    for (int idx = tid; idx < CELL * NB; idx += THREADS) c1sh[idx] = 0.0f;
    if (tid < NB) c2sh[tid] = 0.0f;

    // layer-1 per-thread constants
    float wih[4], bsum[4];
    if (l1) {
        #pragma unroll
        for (int k = 0; k < 4; k++) {
            int g = k * CELL + u;
            wih[k]  = W_ih1[g];
            bsum[k] = b_ih1[g] + b_hh1[g];
        }
    }
    // layer-2 per-lane constants + state
    const int bl2 = tid - L2BASE;          // lane = batch elem (0..31)
    float whh2[4], b2c[4];
    float h2 = 0.0f, c2 = 0.0f;
    if (l2) {
        #pragma unroll
        for (int k = 0; k < 4; k++) {
            whh2[k] = W_hh2[k];
            b2c[k]  = b_ih2[k] + b_hh2[k];
        }
    }

    float c1r[BT];
    #pragma unroll
    for (int bb = 0; bb < BT; bb++) c1r[bb] = 0.0f;

    const float* wp  = Wint + u * WSTRIDE;
    const float* hpA = hA + t8 * 4;        // pairs for b0, b0+1 (16B, own quad)
    const float* hpB = hB + t8 * 4;        // pairs for b0+2, b0+3

    // h write addresses (j-paired layout: unit u -> row u>>1, slot u&1)
    float* hwA = hA + (u >> 1) * 32 + t8 * 4 + (u & 1);
    float* hwB = hB + (u >> 1) * 32 + t8 * 4 + (u & 1);

    // ================= layer-1 step =================
    auto layer1_step = [&](const float* __restrict__ xv, float* __restrict__ hn) {
        unsigned long long Ai[BT], Af[BT], Ag[BT], Ao[BT];
        #pragma unroll
        for (int bb = 0; bb < BT; bb++) { Ai[bb] = 0ull; Af[bb] = 0ull; Ag[bb] = 0ull; Ao[bb] = 0ull; }

        #pragma unroll 2
        for (int j2 = 0; j2 < NJ2; j2++) {
            ulonglong2 wIF = *(const ulonglong2*)(wp + j2 * 8);      // (wi),(wf)
            ulonglong2 wGO = *(const ulonglong2*)(wp + j2 * 8 + 4);  // (wg),(wo)
            ulonglong2 h01 = *(const ulonglong2*)(hpA + j2 * 32);    // b0, b0+1
            ulonglong2 h23 = *(const ulonglong2*)(hpB + j2 * 32);    // b0+2, b0+3
            FMA2(Ai[0], wIF.x, h01.x); FMA2(Af[0], wIF.y, h01.x);
            FMA2(Ag[0], wGO.x, h01.x); FMA2(Ao[0], wGO.y, h01.x);
            FMA2(Ai[1], wIF.x, h01.y); FMA2(Af[1], wIF.y, h01.y);
            FMA2(Ag[1], wGO.x, h01.y); FMA2(Ao[1], wGO.y, h01.y);
            FMA2(Ai[2], wIF.x, h23.x); FMA2(Af[2], wIF.y, h23.x);
            FMA2(Ag[2], wGO.x, h23.x); FMA2(Ao[2], wGO.y, h23.x);
            FMA2(Ai[3], wIF.x, h23.y); FMA2(Af[3], wIF.y, h23.y);
            FMA2(Ag[3], wGO.x, h23.y); FMA2(Ao[3], wGO.y, h23.y);
        }

        #pragma unroll
        for (int bb = 0; bb < BT; bb++) {
            float e, o;
            UNPK2(e, o, Ai[bb]); float gi = e + o;
            UNPK2(e, o, Af[bb]); float gf = e + o;
            UNPK2(e, o, Ag[bb]); float gg = e + o;
            UNPK2(e, o, Ao[bb]); float go = e + o;
            float pi = fmaf(xv[bb], wih[0], gi + bsum[0]);
            float pf = fmaf(xv[bb], wih[1], gf + bsum[1]);
            float pg = fmaf(xv[bb], wih[2], gg + bsum[2]);
            float po = fmaf(xv[bb], wih[3], go + bsum[3]);
            float c  = sigm(pf) * c1r[bb] + sigm(pi) * tanh_f(pg);
            c1r[bb] = c;
            hn[bb]  = sigm(po) * tanh_f(c);
        }
    };

    auto l1_write = [&](const float* __restrict__ hn) {
        hwA[0] = hn[0];
        hwA[2] = hn[1];
        hwB[0] = hn[2];
        hwB[2] = hn[3];
        *(float4*)(c1sh + u * NB + b0) = make_float4(c1r[0], c1r[1], c1r[2], c1r[3]);
    };

    // ================= layer-2 step (one warp, lane = batch) =============
    auto layer2_step = [&](int tt, bool wr_out) {
        const float* cp = c1sh + bl2;
        float di = 0.f, df = 0.f, dg = 0.f, dz = 0.f;
        #pragma unroll 4
        for (int uu = 0; uu < CELL; uu++) {
            float cv  = cp[uu * NB];
            float4 w4 = *(const float4*)(w2i + uu * 4);
            di = fmaf(cv, w4.x, di);
            df = fmaf(cv, w4.y, df);
            dg = fmaf(cv, w4.z, dg);
            dz = fmaf(cv, w4.w, dz);
        }
        float pi = fmaf(h2, whh2[0], di + b2c[0]);
        float pf = fmaf(h2, whh2[1], df + b2c[1]);
        float pg = fmaf(h2, whh2[2], dg + b2c[2]);
        float po = fmaf(h2, whh2[3], dz + b2c[3]);
        float c  = sigm(pf) * c2 + sigm(pi) * tanh_f(pg);
        c2 = c;
        h2 = sigm(po) * tanh_f(c);
        c2sh[bl2] = c;
        if (wr_out) out[(size_t)(bglob0 + bl2) * FUT + (tt - T)] = c;
    };

    __syncthreads();

    // ===== observed phase: l2 pipelined one step behind, 2 syncs/step =====
    for (int t = 0; t < T; ++t) {
        float xv[BT], hn[BT];
        if (l1) {
            float4 x0 = *(const float4*)(input + (size_t)t * Btot + bglob0 + b0);
            xv[0] = x0.x; xv[1] = x0.y; xv[2] = x0.z; xv[3] = x0.w;
            layer1_step(xv, hn);           // reads hA/hB (step t-1)
        } else if (l2 && t > 0) {
            layer2_step(t - 1, false);     // reads c1sh (step t-1)
        }
        __syncthreads();                   // all reads of h/c1 done
        if (l1) l1_write(hn);
        __syncthreads();                   // new h/c1 visible
    }
    // drain layer-2 for step T-1
    if (l2) layer2_step(T - 1, false);
    __syncthreads();

    // ===== future phase: strictly serial, 3 syncs/step =====
    const int TOT = T + FUT;
    for (int t = T; t < TOT; ++t) {
        float xv[BT], hn[BT];
        if (l1) {
            float4 x0 = *(const float4*)(c2sh + b0);
            xv[0] = x0.x; xv[1] = x0.y; xv[2] = x0.z; xv[3] = x0.w;
            layer1_step(xv, hn);
        }
        __syncthreads();
        if (l1) l1_write(hn);
        __syncthreads();
        if (l2) layer2_step(t, true);
        __syncthreads();
    }
}

extern "C" void kernel_launch(void* const* d_in, const int* in_sizes, int n_in,
                              void* d_out, int out_size)
{
    const float* input = (const float*)d_in[0];
    const float* W_ih1 = (const float*)d_in[1];
    const float* W_hh1 = (const float*)d_in[2];
    const float* b_ih1 = (const float*)d_in[3];
    const float* b_hh1 = (const float*)d_in[4];
    const float* W_ih2 = (const float*)d_in[5];
    const float* W_hh2 = (const float*)d_in[6];
    const float* b_ih2 = (const float*)d_in[7];
    const float* b_hh2 = (const float*)d_in[8];
    float* out = (float*)d_out;

    const int Btot = 4096;
    const int T    = in_sizes[0] / Btot;   // 512
    const int FUT  = out_size   / Btot;    // 64

    const int smem = (CELL * WSTRIDE     // Wint      40400
                      + 2 * NJ2 * 32     // hA + hB    3200
                      + CELL * NB        // c1sh       3200
                      + 4 * CELL         // w2i         400
                      + NB)              // c2sh         32
                     * (int)sizeof(float);  // = 188,928 B

    cudaFuncSetAttribute(tsrnn_kernel,
                         cudaFuncAttributeMaxDynamicSharedMemorySize, smem);

    tsrnn_kernel<<<Btot / NB, THREADS, smem>>>(
        input, W_ih1, W_hh1, b_ih1, b_hh1,
        W_ih2, W_hh2, b_ih2, b_hh2,
        out, T, FUT, Btot);
}

// round 6
// speedup vs baseline: 1.4551x; 1.2057x over previous
#include <cuda_runtime.h>
#include <cstddef>

// Two-layer LSTM recurrence, persistent kernel, j-paired f32x2 GEMV.
// R6: R5 data layout (conflict-free, no packs, no duplicated bytes) +
//   - GEMV unrolled in chunks of 10 (LDS immediate offsets, ~zero addr ALU)
//   - single unified loop: future phase pipelined too (GEMV runs without x;
//     x = c2[t-1] is consumed only in the post-sync pointwise).
//
// 128 blocks x 832 threads:
//   tid <  800 : layer-1. unit u = tid>>3, batch group t8 = tid&7, BT=4.
//   tid >= 800 : layer-2 (one warp; lane = batch elem), always one step
//                behind layer-1.

#define CELL     100
#define NJ2      50       // CELL/2 j-pairs
#define NB       32       // batch per block
#define BT       4        // batch per layer-1 thread
#define THREADS  832
#define L2BASE   800
#define WSTRIDE  404      // 404 mod 32 = 20 -> 4 consecutive u hit distinct quads

#define FMA2(acc, a, b) asm("fma.rn.f32x2 %0,%1,%2,%0;" : "+l"(acc) : "l"(a), "l"(b))
#define UNPK2(lo, hi, s) asm("mov.b64 {%0,%1},%2;" : "=f"(lo), "=f"(hi) : "l"(s))

__device__ __forceinline__ float sigm(float x) {
    return 1.0f / (1.0f + __expf(-x));
}
__device__ __forceinline__ float tanh_f(float x) {
    float e = __expf(2.0f * x);
    return 1.0f - 2.0f / (e + 1.0f);
}

__global__ void __launch_bounds__(THREADS, 1)
tsrnn_kernel(const float* __restrict__ input,
             const float* __restrict__ W_ih1, const float* __restrict__ W_hh1,
             const float* __restrict__ b_ih1, const float* __restrict__ b_hh1,
             const float* __restrict__ W_ih2, const float* __restrict__ W_hh2,
             const float* __restrict__ b_ih2, const float* __restrict__ b_hh2,
             float* __restrict__ out, int T, int FUT, int Btot)
{
    extern __shared__ float sm[];
    float* Wint = sm;                     // [100][WSTRIDE]: u*404 + j2*8 + k*2 + p
    float* hA   = Wint + CELL * WSTRIDE;  // [50][32]: pairs (h_e,h_o) for b%4<2
    float* hB   = hA   + NJ2 * 32;        // [50][32]: pairs for b%4>=2
    float* c1sh = hB   + NJ2 * 32;        // [100][32]
    float* w2i  = c1sh + CELL * NB;       // [100][4] gate-interleaved W_ih2
    float* c2sh = w2i  + CELL * 4;        // [32]

    const int tid    = threadIdx.x;
    const int bglob0 = blockIdx.x * NB;

    const bool l1 = (tid < L2BASE);
    const bool l2 = (tid >= L2BASE);
    const int  u  = tid >> 3;             // layer-1 unit (0..99)
    const int  t8 = tid & 7;              // batch subgroup
    const int  b0 = t8 * BT;              // first batch elem

    // ---- stage W_hh1: j-paired, gate-major within pair ----
    for (int idx = tid; idx < 4 * CELL * CELL; idx += THREADS) {
        int uu = idx / 400, rem = idx - uu * 400;
        int j2 = rem >> 3, k = (rem >> 1) & 3, p = rem & 1;
        int j  = 2 * j2 + p;
        Wint[uu * WSTRIDE + j2 * 8 + k * 2 + p] = W_hh1[(k * CELL + uu) * CELL + j];
    }
    for (int idx = tid; idx < 4 * CELL; idx += THREADS) {
        int uu = idx >> 2, k = idx & 3;
        w2i[uu * 4 + k] = W_ih2[k * CELL + uu];
    }
    for (int idx = tid; idx < 2 * NJ2 * 32; idx += THREADS) hA[idx] = 0.0f;
    for (int idx = tid; idx < CELL * NB; idx += THREADS) c1sh[idx] = 0.0f;
    if (tid < NB) c2sh[tid] = 0.0f;

    // layer-1 per-thread constants
    float wih[4], bsum[4];
    if (l1) {
        #pragma unroll
        for (int k = 0; k < 4; k++) {
            int g = k * CELL + u;
            wih[k]  = W_ih1[g];
            bsum[k] = b_ih1[g] + b_hh1[g];
        }
    }
    // layer-2 per-lane constants + state
    const int bl2 = tid - L2BASE;          // lane = batch elem (0..31)
    float whh2[4], b2c[4];
    float h2 = 0.0f, c2 = 0.0f;
    if (l2) {
        #pragma unroll
        for (int k = 0; k < 4; k++) {
            whh2[k] = W_hh2[k];
            b2c[k]  = b_ih2[k] + b_hh2[k];
        }
    }

    float c1r[BT];
    #pragma unroll
    for (int bb = 0; bb < BT; bb++) c1r[bb] = 0.0f;

    const float* wp  = Wint + u * WSTRIDE;
    const float* hpA = hA + t8 * 4;        // pairs for b0, b0+1 (16B, own quad)
    const float* hpB = hB + t8 * 4;        // pairs for b0+2, b0+3

    // h write addresses (j-paired layout: unit u -> row u>>1, slot u&1)
    float* hwA = hA + (u >> 1) * 32 + t8 * 4 + (u & 1);
    float* hwB = hB + (u >> 1) * 32 + t8 * 4 + (u & 1);

    __syncthreads();

    const int TOT = T + FUT;
    for (int t = 0; t < TOT; ++t) {
        const bool fut = (t >= T);
        float xv[BT], hn[BT];
        unsigned long long Ai[BT], Af[BT], Ag[BT], Ao[BT];

        if (l1) {
            if (!fut) {
                float4 x0 = *(const float4*)(input + (size_t)t * Btot + bglob0 + b0);
                xv[0] = x0.x; xv[1] = x0.y; xv[2] = x0.z; xv[3] = x0.w;
            }
            // ---- GEMV on h[t-1]; x not needed yet ----
            #pragma unroll
            for (int bb = 0; bb < BT; bb++) { Ai[bb] = 0ull; Af[bb] = 0ull; Ag[bb] = 0ull; Ao[bb] = 0ull; }

            #pragma unroll 10
            for (int j2 = 0; j2 < NJ2; j2++) {
                ulonglong2 wIF = *(const ulonglong2*)(wp + j2 * 8);      // (wi),(wf)
                ulonglong2 wGO = *(const ulonglong2*)(wp + j2 * 8 + 4);  // (wg),(wo)
                ulonglong2 h01 = *(const ulonglong2*)(hpA + j2 * 32);    // b0, b0+1
                ulonglong2 h23 = *(const ulonglong2*)(hpB + j2 * 32);    // b0+2, b0+3
                FMA2(Ai[0], wIF.x, h01.x); FMA2(Af[0], wIF.y, h01.x);
                FMA2(Ag[0], wGO.x, h01.x); FMA2(Ao[0], wGO.y, h01.x);
                FMA2(Ai[1], wIF.x, h01.y); FMA2(Af[1], wIF.y, h01.y);
                FMA2(Ag[1], wGO.x, h01.y); FMA2(Ao[1], wGO.y, h01.y);
                FMA2(Ai[2], wIF.x, h23.x); FMA2(Af[2], wIF.y, h23.x);
                FMA2(Ag[2], wGO.x, h23.x); FMA2(Ao[2], wGO.y, h23.x);
                FMA2(Ai[3], wIF.x, h23.y); FMA2(Af[3], wIF.y, h23.y);
                FMA2(Ag[3], wGO.x, h23.y); FMA2(Ao[3], wGO.y, h23.y);
            }
        } else if (l2 && t > 0) {
            // ---- layer-2 for step t-1 (concurrent with layer-1's GEMV) ----
            const int tt = t - 1;
            const float* cp = c1sh + bl2;
            float di = 0.f, df = 0.f, dg = 0.f, dz = 0.f;
            #pragma unroll 10
            for (int uu = 0; uu < CELL; uu++) {
                float cv  = cp[uu * NB];
                float4 w4 = *(const float4*)(w2i + uu * 4);
                di = fmaf(cv, w4.x, di);
                df = fmaf(cv, w4.y, df);
                dg = fmaf(cv, w4.z, dg);
                dz = fmaf(cv, w4.w, dz);
            }
            float pi = fmaf(h2, whh2[0], di + b2c[0]);
            float pf = fmaf(h2, whh2[1], df + b2c[1]);
            float pg = fmaf(h2, whh2[2], dg + b2c[2]);
            float po = fmaf(h2, whh2[3], dz + b2c[3]);
            float c  = sigm(pf) * c2 + sigm(pi) * tanh_f(pg);
            c2 = c;
            h2 = sigm(po) * tanh_f(c);
            c2sh[bl2] = c;
            if (tt >= T) out[(size_t)(bglob0 + bl2) * FUT + (tt - T)] = c;
        }

        __syncthreads();   // GEMV/c1 reads done; c2sh holds c2[t-1]

        if (l1) {
            if (fut) {
                float4 x0 = *(const float4*)(c2sh + b0);
                xv[0] = x0.x; xv[1] = x0.y; xv[2] = x0.z; xv[3] = x0.w;
            }
            #pragma unroll
            for (int bb = 0; bb < BT; bb++) {
                float e, o;
                UNPK2(e, o, Ai[bb]); float gi = e + o;
                UNPK2(e, o, Af[bb]); float gf = e + o;
                UNPK2(e, o, Ag[bb]); float gg = e + o;
                UNPK2(e, o, Ao[bb]); float go = e + o;
                float pi = fmaf(xv[bb], wih[0], gi + bsum[0]);
                float pf = fmaf(xv[bb], wih[1], gf + bsum[1]);
                float pg = fmaf(xv[bb], wih[2], gg + bsum[2]);
                float po = fmaf(xv[bb], wih[3], go + bsum[3]);
                float c  = sigm(pf) * c1r[bb] + sigm(pi) * tanh_f(pg);
                c1r[bb] = c;
                hn[bb]  = sigm(po) * tanh_f(c);
            }
            hwA[0] = hn[0];
            hwA[2] = hn[1];
            hwB[0] = hn[2];
            hwB[2] = hn[3];
            *(float4*)(c1sh + u * NB + b0) = make_float4(c1r[0], c1r[1], c1r[2], c1r[3]);
        }

        __syncthreads();   // new h/c1/c2 visible for next step
    }

    // drain: layer-2 for the final step TOT-1
    if (l2) {
        const int tt = TOT - 1;
        const float* cp = c1sh + bl2;
        float di = 0.f, df = 0.f, dg = 0.f, dz = 0.f;
        #pragma unroll 10
        for (int uu = 0; uu < CELL; uu++) {
            float cv  = cp[uu * NB];
            float4 w4 = *(const float4*)(w2i + uu * 4);
            di = fmaf(cv, w4.x, di);
            df = fmaf(cv, w4.y, df);
            dg = fmaf(cv, w4.z, dg);
            dz = fmaf(cv, w4.w, dz);
        }
        float pi = fmaf(h2, whh2[0], di + b2c[0]);
        float pf = fmaf(h2, whh2[1], df + b2c[1]);
        float pg = fmaf(h2, whh2[2], dg + b2c[2]);
        float po = fmaf(h2, whh2[3], dz + b2c[3]);
        float c  = sigm(pf) * c2 + sigm(pi) * tanh_f(pg);
        out[(size_t)(bglob0 + bl2) * FUT + (tt - T)] = c;
    }
}

extern "C" void kernel_launch(void* const* d_in, const int* in_sizes, int n_in,
                              void* d_out, int out_size)
{
    const float* input = (const float*)d_in[0];
    const float* W_ih1 = (const float*)d_in[1];
    const float* W_hh1 = (const float*)d_in[2];
    const float* b_ih1 = (const float*)d_in[3];
    const float* b_hh1 = (const float*)d_in[4];
    const float* W_ih2 = (const float*)d_in[5];
    const float* W_hh2 = (const float*)d_in[6];
    const float* b_ih2 = (const float*)d_in[7];
    const float* b_hh2 = (const float*)d_in[8];
    float* out = (float*)d_out;

    const int Btot = 4096;
    const int T    = in_sizes[0] / Btot;   // 512
    const int FUT  = out_size   / Btot;    // 64

    const int smem = (CELL * WSTRIDE     // Wint      40400
                      + 2 * NJ2 * 32     // hA + hB    3200
                      + CELL * NB        // c1sh       3200
                      + 4 * CELL         // w2i         400
                      + NB)              // c2sh         32
                     * (int)sizeof(float);  // = 188,928 B

    cudaFuncSetAttribute(tsrnn_kernel,
                         cudaFuncAttributeMaxDynamicSharedMemorySize, smem);

    tsrnn_kernel<<<Btot / NB, THREADS, smem>>>(
        input, W_ih1, W_hh1, b_ih1, b_hh1,
        W_ih2, W_hh2, b_ih2, b_hh2,
        out, T, FUT, Btot);
}